// round 14
// baseline (speedup 1.0000x reference)
#include <cuda_runtime.h>
#include <cuda_bf16.h>
#include <cstdint>

#define N_NODES 20000
#define N_EDGES 640000
#define C 128
#define NUM_GRAPHS 64
#define CAP 128                        // bucket capacity per node (max deg ~58)

// ---------------- scratch (no allocations allowed) ----------------
__device__ __nv_bfloat16 g_xb[N_NODES * C];  // bf16 x (gather source, layer 1)
__device__ __nv_bfloat16 g_hb[N_NODES * C];  // bf16 h1 (gather source, layer 2)
__device__ float g_agg[N_NODES * C];         // tf32-rounded gather output
__device__ float g_Wt[4][C * C];       // tf32-pre-rounded W1a, W1b, W2a, W2b
__device__ float g_gsum[NUM_GRAPHS * C];
__device__ float g_gcnt[NUM_GRAPHS];
__device__ int   g_src[N_EDGES];
__device__ int   g_dst[N_EDGES];
__device__ int   g_rank[N_EDGES];
__device__ int   g_csrc[N_NODES * CAP];
__device__ int   g_deg[N_NODES];
__device__ int   g_batch[N_NODES];
__device__ int   g_is64;

// ---------------- helpers ----------------
__device__ __forceinline__ float tf32r(float x) {
    uint32_t u; asm("cvt.rna.tf32.f32 %0, %1;" : "=r"(u) : "f"(x));
    return __uint_as_float(u);
}
__device__ __forceinline__ void mma8(float* c, uint32_t a0, uint32_t a1, uint32_t a2,
                                     uint32_t a3, uint32_t b0, uint32_t b1) {
    asm volatile("mma.sync.aligned.m16n8k8.row.col.f32.tf32.tf32.f32 "
                 "{%0,%1,%2,%3}, {%4,%5,%6,%7}, {%8,%9}, {%0,%1,%2,%3};"
                 : "+f"(c[0]), "+f"(c[1]), "+f"(c[2]), "+f"(c[3])
                 : "r"(a0), "r"(a1), "r"(a2), "r"(a3), "r"(b0), "r"(b1));
}
// bf16 -> f32 is a 16-bit shift; accumulate 8 channels as 4 packed f32x2 adds.
__device__ __forceinline__ void bf8_acc(const __nv_bfloat16* p, unsigned long long* acc) {
    uint4 u = *(const uint4*)p;
    unsigned long long v0, v1, v2, v3;
    asm("mov.b64 %0, {%1, %2};" : "=l"(v0)
        : "r"(u.x << 16), "r"(u.x & 0xffff0000u));
    asm("mov.b64 %0, {%1, %2};" : "=l"(v1)
        : "r"(u.y << 16), "r"(u.y & 0xffff0000u));
    asm("mov.b64 %0, {%1, %2};" : "=l"(v2)
        : "r"(u.z << 16), "r"(u.z & 0xffff0000u));
    asm("mov.b64 %0, {%1, %2};" : "=l"(v3)
        : "r"(u.w << 16), "r"(u.w & 0xffff0000u));
    asm("add.rn.f32x2 %0, %0, %1;" : "+l"(acc[0]) : "l"(v0));
    asm("add.rn.f32x2 %0, %0, %1;" : "+l"(acc[1]) : "l"(v1));
    asm("add.rn.f32x2 %0, %0, %1;" : "+l"(acc[2]) : "l"(v2));
    asm("add.rn.f32x2 %0, %0, %1;" : "+l"(acc[3]) : "l"(v3));
}

// ---------------- mega setup ----------------
__global__ void mega_setup(const float* __restrict__ x,
                           const float* __restrict__ W1a, const float* __restrict__ W1b,
                           const float* __restrict__ W2a, const float* __restrict__ W2b,
                           const int* __restrict__ eidx_raw) {
    int i = blockIdx.x * blockDim.x + threadIdx.x;
    if (i < N_NODES * C / 8) {
        float4 a = ((const float4*)x)[i * 2];
        float4 b = ((const float4*)x)[i * 2 + 1];
        uint4 o;
        __nv_bfloat162 p0 = __float22bfloat162_rn(make_float2(a.x, a.y));
        __nv_bfloat162 p1 = __float22bfloat162_rn(make_float2(a.z, a.w));
        __nv_bfloat162 p2 = __float22bfloat162_rn(make_float2(b.x, b.y));
        __nv_bfloat162 p3 = __float22bfloat162_rn(make_float2(b.z, b.w));
        o.x = *reinterpret_cast<uint32_t*>(&p0);
        o.y = *reinterpret_cast<uint32_t*>(&p1);
        o.z = *reinterpret_cast<uint32_t*>(&p2);
        o.w = *reinterpret_cast<uint32_t*>(&p3);
        ((uint4*)g_xb)[i] = o;
    }
    if (i < 16384) {
        int which = i >> 12;
        int idx = i & 4095;
        const float* src = (which == 0) ? W1a : (which == 1) ? W1b
                         : (which == 2) ? W2a : W2b;
        float4 v = ((const float4*)src)[idx];
        ((float4*)g_Wt[which])[idx] =
            make_float4(tf32r(v.x), tf32r(v.y), tf32r(v.z), tf32r(v.w));
    }
    if (i < N_NODES) g_deg[i] = 0;
    if (i < NUM_GRAPHS * C) g_gsum[i] = 0.f;
    if (i < NUM_GRAPHS) g_gcnt[i] = 0.f;
    if (i == 0) {
        int any = 0;
#pragma unroll
        for (int k = 1; k < 128; k += 2) any |= eidx_raw[k];
        g_is64 = (any == 0) ? 1 : 0;
    }
}

// ---------------- convert indices + degree histogram ----------------
__global__ void convert_indices(const void* __restrict__ eidx,
                                const void* __restrict__ batch) {
    int i0 = (blockIdx.x * blockDim.x + threadIdx.x) * 4;
    if (g_is64) {
        const long long* e = (const long long*)eidx;
        if (i0 < N_EDGES) {
            longlong2 s01 = *(const longlong2*)&e[i0];
            longlong2 s23 = *(const longlong2*)&e[i0 + 2];
            longlong2 d01 = *(const longlong2*)&e[N_EDGES + i0];
            longlong2 d23 = *(const longlong2*)&e[N_EDGES + i0 + 2];
            int4 s = make_int4((int)s01.x, (int)s01.y, (int)s23.x, (int)s23.y);
            int4 d = make_int4((int)d01.x, (int)d01.y, (int)d23.x, (int)d23.y);
            *(int4*)&g_src[i0] = s;
            *(int4*)&g_dst[i0] = d;
            int4 r;
            r.x = atomicAdd(&g_deg[d.x], 1);
            r.y = atomicAdd(&g_deg[d.y], 1);
            r.z = atomicAdd(&g_deg[d.z], 1);
            r.w = atomicAdd(&g_deg[d.w], 1);
            *(int4*)&g_rank[i0] = r;
        }
        if (i0 < N_NODES) {
            const long long* b = (const long long*)batch;
            longlong2 b01 = *(const longlong2*)&b[i0];
            longlong2 b23 = *(const longlong2*)&b[i0 + 2];
            int4 g = make_int4((int)b01.x, (int)b01.y, (int)b23.x, (int)b23.y);
            *(int4*)&g_batch[i0] = g;
            atomicAdd(&g_gcnt[g.x], 1.f); atomicAdd(&g_gcnt[g.y], 1.f);
            atomicAdd(&g_gcnt[g.z], 1.f); atomicAdd(&g_gcnt[g.w], 1.f);
        }
    } else {
        const int* e = (const int*)eidx;
        if (i0 < N_EDGES) {
            int4 s = *(const int4*)&e[i0];
            int4 d = *(const int4*)&e[N_EDGES + i0];
            *(int4*)&g_src[i0] = s;
            *(int4*)&g_dst[i0] = d;
            int4 r;
            r.x = atomicAdd(&g_deg[d.x], 1);
            r.y = atomicAdd(&g_deg[d.y], 1);
            r.z = atomicAdd(&g_deg[d.z], 1);
            r.w = atomicAdd(&g_deg[d.w], 1);
            *(int4*)&g_rank[i0] = r;
        }
        if (i0 < N_NODES) {
            int4 g = *(const int4*)&((const int*)batch)[i0];
            *(int4*)&g_batch[i0] = g;
            atomicAdd(&g_gcnt[g.x], 1.f); atomicAdd(&g_gcnt[g.y], 1.f);
            atomicAdd(&g_gcnt[g.z], 1.f); atomicAdd(&g_gcnt[g.w], 1.f);
        }
    }
}

// ---------------- bucket fill (atomic-free) ----------------
__global__ void fill_csr() {
    int i0 = (blockIdx.x * blockDim.x + threadIdx.x) * 4;
    if (i0 + 3 < N_EDGES) {
        int4 d = *(const int4*)&g_dst[i0];
        int4 s = *(const int4*)&g_src[i0];
        int4 r = *(const int4*)&g_rank[i0];
        if (r.x < CAP) g_csrc[d.x * CAP + r.x] = s.x;
        if (r.y < CAP) g_csrc[d.y * CAP + r.y] = s.y;
        if (r.z < CAP) g_csrc[d.z * CAP + r.z] = s.z;
        if (r.w < CAP) g_csrc[d.w * CAP + r.w] = s.w;
    } else {
        for (int i = i0; i < N_EDGES; ++i) {
            int r = g_rank[i];
            if (r < CAP) g_csrc[g_dst[i] * CAP + r] = g_src[i];
        }
    }
}

// ---------------- standalone gather: max-occupancy (64 warps/SM) ----------------
// 2 nodes per warp; half-warps pair edges; LDG.128 (8 bf16 channels/lane);
// packed f32x2 accumulation. 4-edge chunks keep regs <= 32 for 8 CTAs/SM.
__global__ void __launch_bounds__(256, 8) gather_kernel(
    const __nv_bfloat16* __restrict__ feat, float* __restrict__ agg)
{
    const int t = threadIdx.x;
    const int lane = t & 31;
    const int w = t >> 5;
    const int half = lane >> 4;           // 0 or 1
    const int chb = (lane & 15) * 8;      // channel base
#pragma unroll
    for (int i = 0; i < 2; ++i) {
        int node = blockIdx.x * 16 + w * 2 + i;   // grid 1250 -> exact
        unsigned long long acc[4];
        float z = 0.f;
        asm("mov.b64 %0, {%1, %1};" : "=l"(acc[0]) : "f"(z));
        acc[1] = acc[0]; acc[2] = acc[0]; acc[3] = acc[0];
        if (half == 0)                    // self term (GIN eps=0)
            bf8_acc(&feat[(size_t)node * C + chb], acc);
        const int* adj = &g_csrc[node * CAP];
        int deg = g_deg[node];
        if (deg > CAP) deg = CAP;
        int e = 0;
        for (; e + 4 <= deg; e += 4) {    // 2 paired loads in flight
            int s0 = adj[e + half];
            int s1 = adj[e + 2 + half];
            bf8_acc(&feat[(size_t)s0 * C + chb], acc);
            bf8_acc(&feat[(size_t)s1 * C + chb], acc);
        }
        if (e + 2 <= deg) {
            int s = adj[e + half];
            bf8_acc(&feat[(size_t)s * C + chb], acc);
            e += 2;
        }
        if (e < deg && half == 0)
            bf8_acc(&feat[(size_t)adj[e] * C + chb], acc);
        // unpack, combine halves, tf32-round, store
        float av[8];
#pragma unroll
        for (int j = 0; j < 4; ++j) {
            uint32_t lo, hi;
            asm("mov.b64 {%0, %1}, %2;" : "=r"(lo), "=r"(hi) : "l"(acc[j]));
            av[j * 2]     = __uint_as_float(lo);
            av[j * 2 + 1] = __uint_as_float(hi);
        }
#pragma unroll
        for (int j = 0; j < 8; ++j)
            av[j] += __shfl_xor_sync(0xFFFFFFFFu, av[j], 16);
        float4 o = (half == 0)
            ? make_float4(tf32r(av[0]), tf32r(av[1]), tf32r(av[2]), tf32r(av[3]))
            : make_float4(tf32r(av[4]), tf32r(av[5]), tf32r(av[6]), tf32r(av[7]));
        *(float4*)&agg[(size_t)node * C + chb + half * 4] = o;
    }
}

// ---------------- MLP kernel: GEMM1 + ReLU + GEMM2 (+pool) ----------------
#define TILE_ROWS 32
#define ASTR 132
#define WSTR 136
#define CONV_SMEM ((128 * WSTR + TILE_ROWS * ASTR) * 4)

__device__ __forceinline__ void gemm_tile(const float* __restrict__ As,
                                          const float* __restrict__ Ws,
                                          float acc[4][4],
                                          int m_base, int n_base, int qid, int tid4)
{
#pragma unroll
    for (int nt = 0; nt < 4; ++nt)
#pragma unroll
        for (int j = 0; j < 4; ++j) acc[nt][j] = 0.f;

#pragma unroll
    for (int k0 = 0; k0 < 128; k0 += 8) {
        const float* ar0 = &As[(m_base + qid) * ASTR + k0 + tid4];
        const float* ar1 = &As[(m_base + qid + 8) * ASTR + k0 + tid4];
        uint32_t a0 = __float_as_uint(ar0[0]);
        uint32_t a1 = __float_as_uint(ar1[0]);
        uint32_t a2 = __float_as_uint(ar0[4]);
        uint32_t a3 = __float_as_uint(ar1[4]);
        const float* wr0 = &Ws[(k0 + tid4) * WSTR + n_base + qid];
        const float* wr1 = wr0 + 4 * WSTR;
#pragma unroll
        for (int nt = 0; nt < 4; ++nt) {
            uint32_t b0 = __float_as_uint(wr0[nt * 8]);
            uint32_t b1 = __float_as_uint(wr1[nt * 8]);
            mma8(acc[nt], a0, a1, a2, a3, b0, b1);
        }
    }
}

__global__ void __launch_bounds__(256, 2) mlp_kernel(
    const float* __restrict__ agg,
    const float* __restrict__ Wa, const float* __restrict__ ba,
    const float* __restrict__ Wb, const float* __restrict__ bb,
    __nv_bfloat16* __restrict__ outb, int do_pool)
{
    extern __shared__ float sm[];
    float* Ws = sm;                       // [128][WSTR]
    float* As = sm + 128 * WSTR;          // [32][ASTR]

    const int t = threadIdx.x;
    const int m0 = blockIdx.x * TILE_ROWS;
    const int lane = t & 31;
    const int w = t >> 5;

    // load Wa (pure copy, pre-rounded)
#pragma unroll
    for (int i = 0; i < 16; ++i) {
        int idx = t + i * 256;
        float4 v = ((const float4*)Wa)[idx];
        *(float4*)&Ws[(idx >> 5) * WSTR + (idx & 31) * 4] = v;
    }
    // load A tile (coalesced; already tf32-rounded)
#pragma unroll
    for (int i = 0; i < 4; ++i) {
        int idx = t + i * 256;            // 1024 float4
        int r = idx >> 5;
        int c4 = idx & 31;
        float4 v = ((const float4*)agg)[(size_t)(m0 + r) * 32 + c4];
        *(float4*)&As[r * ASTR + c4 * 4] = v;
    }
    __syncthreads();

    const int warp_m = w & 1;
    const int warp_n = w >> 1;
    const int m_base = warp_m * 16;
    const int n_base = warp_n * 32;
    const int qid = lane >> 2;
    const int tid4 = lane & 3;

    float acc[4][4];

    // GEMM1
    gemm_tile(As, Ws, acc, m_base, n_base, qid, tid4);
    __syncthreads();

    // t = tf32(relu(acc + ba)) -> As ; reload Ws with Wb
#pragma unroll
    for (int nt = 0; nt < 4; ++nt) {
        int col = n_base + nt * 8 + 2 * tid4;
        float2 bv = *(const float2*)&ba[col];
        int r0 = m_base + qid, r1 = r0 + 8;
        *(float2*)&As[r0 * ASTR + col] =
            make_float2(tf32r(fmaxf(acc[nt][0] + bv.x, 0.f)),
                        tf32r(fmaxf(acc[nt][1] + bv.y, 0.f)));
        *(float2*)&As[r1 * ASTR + col] =
            make_float2(tf32r(fmaxf(acc[nt][2] + bv.x, 0.f)),
                        tf32r(fmaxf(acc[nt][3] + bv.y, 0.f)));
    }
#pragma unroll
    for (int i = 0; i < 16; ++i) {
        int idx = t + i * 256;
        float4 v = ((const float4*)Wb)[idx];
        *(float4*)&Ws[(idx >> 5) * WSTR + (idx & 31) * 4] = v;
    }
    __syncthreads();

    // GEMM2
    gemm_tile(As, Ws, acc, m_base, n_base, qid, tid4);

    // epilogue
    const int rowA = m0 + m_base + qid;
    const int rowB = rowA + 8;
    if (do_pool) {
        int gA = g_batch[rowA];
        int gB = g_batch[rowB];
#pragma unroll
        for (int nt = 0; nt < 4; ++nt) {
            int col = n_base + nt * 8 + 2 * tid4;
            float2 bv = *(const float2*)&bb[col];
            float v0 = fmaxf(acc[nt][0] + bv.x, 0.f);
            float v1 = fmaxf(acc[nt][1] + bv.y, 0.f);
            float v2 = fmaxf(acc[nt][2] + bv.x, 0.f);
            float v3 = fmaxf(acc[nt][3] + bv.y, 0.f);
            if (gA == gB) {
                atomicAdd(&g_gsum[gA * C + col],     v0 + v2);
                atomicAdd(&g_gsum[gA * C + col + 1], v1 + v3);
            } else {
                atomicAdd(&g_gsum[gA * C + col],     v0);
                atomicAdd(&g_gsum[gA * C + col + 1], v1);
                atomicAdd(&g_gsum[gB * C + col],     v2);
                atomicAdd(&g_gsum[gB * C + col + 1], v3);
            }
        }
    } else {
#pragma unroll
        for (int nt = 0; nt < 4; ++nt) {
            int col = n_base + nt * 8 + 2 * tid4;
            float2 bv = *(const float2*)&bb[col];
            __nv_bfloat162 pA = __float22bfloat162_rn(
                make_float2(fmaxf(acc[nt][0] + bv.x, 0.f), fmaxf(acc[nt][1] + bv.y, 0.f)));
            __nv_bfloat162 pB = __float22bfloat162_rn(
                make_float2(fmaxf(acc[nt][2] + bv.x, 0.f), fmaxf(acc[nt][3] + bv.y, 0.f)));
            *(__nv_bfloat162*)&outb[(size_t)rowA * C + col] = pA;
            *(__nv_bfloat162*)&outb[(size_t)rowB * C + col] = pB;
        }
    }
}

// ---------------- finalize ----------------
__global__ void finalize_kernel(const float* __restrict__ fc_w,
                                const float* __restrict__ fc_b,
                                float* __restrict__ out) {
    int g = blockIdx.x;
    int t = threadIdx.x;  // 128
    float v = g_gsum[g * C + t] * fc_w[t];
#pragma unroll
    for (int o = 16; o > 0; o >>= 1) v += __shfl_down_sync(0xFFFFFFFFu, v, o);
    __shared__ float ws[4];
    if ((t & 31) == 0) ws[t >> 5] = v;
    __syncthreads();
    if (t == 0) {
        float s = ws[0] + ws[1] + ws[2] + ws[3];
        out[g] = s / fmaxf(g_gcnt[g], 1.0f) + fc_b[0];
    }
}

// ---------------- launch ----------------
extern "C" void kernel_launch(void* const* d_in, const int* in_sizes, int n_in,
                              void* d_out, int out_size) {
    const float* x    = (const float*)d_in[0];
    const void*  eidx = d_in[1];
    const void*  batv = d_in[2];
    const float* W1a  = (const float*)d_in[3];
    const float* b1a  = (const float*)d_in[4];
    const float* W1b  = (const float*)d_in[5];
    const float* b1b  = (const float*)d_in[6];
    const float* W2a  = (const float*)d_in[7];
    const float* b2a  = (const float*)d_in[8];
    const float* W2b  = (const float*)d_in[9];
    const float* b2b  = (const float*)d_in[10];
    const float* fcw  = (const float*)d_in[11];
    const float* fcb  = (const float*)d_in[12];
    float* out = (float*)d_out;
    (void)in_sizes; (void)n_in; (void)out_size;

    cudaFuncSetAttribute(mlp_kernel,
                         cudaFuncAttributeMaxDynamicSharedMemorySize, CONV_SMEM);

    float *p_Wt, *p_agg;
    __nv_bfloat16 *p_xb, *p_hb;
    cudaGetSymbolAddress((void**)&p_Wt,  g_Wt);
    cudaGetSymbolAddress((void**)&p_agg, g_agg);
    cudaGetSymbolAddress((void**)&p_xb,  g_xb);
    cudaGetSymbolAddress((void**)&p_hb,  g_hb);

    const int mlp_blocks = N_NODES / TILE_ROWS;      // 625, exact
    const int gather_blocks = N_NODES / 16;          // 1250, exact

    // #1: setup + W preround + x->bf16
    mega_setup<<<(N_NODES * C / 8 + 255) / 256, 256>>>(
        x, W1a, W1b, W2a, W2b, (const int*)eidx);
    // #2: index convert + degree histogram
    convert_indices<<<(N_EDGES / 4 + 255) / 256, 256>>>(eidx, batv);
    // #3: bucket fill
    fill_csr<<<(N_EDGES / 4 + 255) / 256, 256>>>();
    // #4: gather layer 1
    gather_kernel<<<gather_blocks, 256>>>(p_xb, p_agg);
    // #5: MLP layer 1 -> h1 (bf16)
    mlp_kernel<<<mlp_blocks, 256, CONV_SMEM>>>(
        p_agg, p_Wt + 0 * C * C, b1a, p_Wt + 1 * C * C, b1b, p_hb, 0);
    // #6 (ncu-profiled): gather layer 2
    gather_kernel<<<gather_blocks, 256>>>(p_hb, p_agg);
    // #7: MLP layer 2 (+ fused pool)
    mlp_kernel<<<mlp_blocks, 256, CONV_SMEM>>>(
        p_agg, p_Wt + 2 * C * C, b2a, p_Wt + 3 * C * C, b2b, nullptr, 1);
    // #8: finalize
    finalize_kernel<<<NUM_GRAPHS, C>>>(fcw, fcb, out);
}

// round 15
// speedup vs baseline: 1.0716x; 1.0716x over previous
#include <cuda_runtime.h>
#include <cuda_bf16.h>
#include <cstdint>

#define N_NODES 20000
#define N_EDGES 640000
#define C 128
#define NUM_GRAPHS 64
#define CAP 128                        // bucket capacity per node (max deg ~58)

// ---------------- scratch (no allocations allowed) ----------------
__device__ __nv_bfloat16 g_xb[N_NODES * C];  // bf16 x (gather source, layer 1)
__device__ __nv_bfloat16 g_hb[N_NODES * C];  // bf16 h1 (gather source, layer 2)
__device__ float g_agg[N_NODES * C];         // tf32-rounded gather output
__device__ float g_Wt[4][C * C];       // tf32-pre-rounded W1a, W1b, W2a, W2b
__device__ float g_gsum[NUM_GRAPHS * C];
__device__ float g_gcnt[NUM_GRAPHS];
__device__ int   g_src[N_EDGES];
__device__ int   g_dst[N_EDGES];
__device__ int   g_rank[N_EDGES];
__device__ int   g_csrc[N_NODES * CAP];
__device__ int   g_deg[N_NODES];
__device__ int   g_batch[N_NODES];
__device__ int   g_is64;

// ---------------- helpers ----------------
__device__ __forceinline__ float tf32r(float x) {
    uint32_t u; asm("cvt.rna.tf32.f32 %0, %1;" : "=r"(u) : "f"(x));
    return __uint_as_float(u);
}
__device__ __forceinline__ void mma8(float* c, uint32_t a0, uint32_t a1, uint32_t a2,
                                     uint32_t a3, uint32_t b0, uint32_t b1) {
    asm volatile("mma.sync.aligned.m16n8k8.row.col.f32.tf32.tf32.f32 "
                 "{%0,%1,%2,%3}, {%4,%5,%6,%7}, {%8,%9}, {%0,%1,%2,%3};"
                 : "+f"(c[0]), "+f"(c[1]), "+f"(c[2]), "+f"(c[3])
                 : "r"(a0), "r"(a1), "r"(a2), "r"(a3), "r"(b0), "r"(b1));
}
// bf16 -> f32 is a 16-bit shift; accumulate 8 channels as 4 packed f32x2 adds.
__device__ __forceinline__ void bf8_acc(const __nv_bfloat16* p, unsigned long long* acc) {
    uint4 u = *(const uint4*)p;
    unsigned long long v0, v1, v2, v3;
    asm("mov.b64 %0, {%1, %2};" : "=l"(v0)
        : "r"(u.x << 16), "r"(u.x & 0xffff0000u));
    asm("mov.b64 %0, {%1, %2};" : "=l"(v1)
        : "r"(u.y << 16), "r"(u.y & 0xffff0000u));
    asm("mov.b64 %0, {%1, %2};" : "=l"(v2)
        : "r"(u.z << 16), "r"(u.z & 0xffff0000u));
    asm("mov.b64 %0, {%1, %2};" : "=l"(v3)
        : "r"(u.w << 16), "r"(u.w & 0xffff0000u));
    asm("add.rn.f32x2 %0, %0, %1;" : "+l"(acc[0]) : "l"(v0));
    asm("add.rn.f32x2 %0, %0, %1;" : "+l"(acc[1]) : "l"(v1));
    asm("add.rn.f32x2 %0, %0, %1;" : "+l"(acc[2]) : "l"(v2));
    asm("add.rn.f32x2 %0, %0, %1;" : "+l"(acc[3]) : "l"(v3));
}

// ---------------- mega setup ----------------
__global__ void mega_setup(const float* __restrict__ x,
                           const float* __restrict__ W1a, const float* __restrict__ W1b,
                           const float* __restrict__ W2a, const float* __restrict__ W2b,
                           const int* __restrict__ eidx_raw) {
    int i = blockIdx.x * blockDim.x + threadIdx.x;
    if (i < N_NODES * C / 8) {
        float4 a = ((const float4*)x)[i * 2];
        float4 b = ((const float4*)x)[i * 2 + 1];
        uint4 o;
        __nv_bfloat162 p0 = __float22bfloat162_rn(make_float2(a.x, a.y));
        __nv_bfloat162 p1 = __float22bfloat162_rn(make_float2(a.z, a.w));
        __nv_bfloat162 p2 = __float22bfloat162_rn(make_float2(b.x, b.y));
        __nv_bfloat162 p3 = __float22bfloat162_rn(make_float2(b.z, b.w));
        o.x = *reinterpret_cast<uint32_t*>(&p0);
        o.y = *reinterpret_cast<uint32_t*>(&p1);
        o.z = *reinterpret_cast<uint32_t*>(&p2);
        o.w = *reinterpret_cast<uint32_t*>(&p3);
        ((uint4*)g_xb)[i] = o;
    }
    if (i < 16384) {
        int which = i >> 12;
        int idx = i & 4095;
        const float* src = (which == 0) ? W1a : (which == 1) ? W1b
                         : (which == 2) ? W2a : W2b;
        float4 v = ((const float4*)src)[idx];
        ((float4*)g_Wt[which])[idx] =
            make_float4(tf32r(v.x), tf32r(v.y), tf32r(v.z), tf32r(v.w));
    }
    if (i < N_NODES) g_deg[i] = 0;
    if (i < NUM_GRAPHS * C) g_gsum[i] = 0.f;
    if (i < NUM_GRAPHS) g_gcnt[i] = 0.f;
    if (i == 0) {
        int any = 0;
#pragma unroll
        for (int k = 1; k < 128; k += 2) any |= eidx_raw[k];
        g_is64 = (any == 0) ? 1 : 0;
    }
}

// ---------------- convert indices + degree histogram (2 edges/thread) ----------------
__global__ void convert_indices(const void* __restrict__ eidx,
                                const void* __restrict__ batch) {
    int i0 = (blockIdx.x * blockDim.x + threadIdx.x) * 2;
    if (g_is64) {
        const long long* e = (const long long*)eidx;
        if (i0 < N_EDGES) {
            longlong2 s01 = *(const longlong2*)&e[i0];
            longlong2 d01 = *(const longlong2*)&e[N_EDGES + i0];
            int2 s = make_int2((int)s01.x, (int)s01.y);
            int2 d = make_int2((int)d01.x, (int)d01.y);
            *(int2*)&g_src[i0] = s;
            *(int2*)&g_dst[i0] = d;
            int2 r;
            r.x = atomicAdd(&g_deg[d.x], 1);
            r.y = atomicAdd(&g_deg[d.y], 1);
            *(int2*)&g_rank[i0] = r;
        }
        if (i0 < N_NODES) {
            const long long* b = (const long long*)batch;
            longlong2 b01 = *(const longlong2*)&b[i0];
            int2 g = make_int2((int)b01.x, (int)b01.y);
            *(int2*)&g_batch[i0] = g;
            atomicAdd(&g_gcnt[g.x], 1.f); atomicAdd(&g_gcnt[g.y], 1.f);
        }
    } else {
        const int* e = (const int*)eidx;
        if (i0 < N_EDGES) {
            int2 s = *(const int2*)&e[i0];
            int2 d = *(const int2*)&e[N_EDGES + i0];
            *(int2*)&g_src[i0] = s;
            *(int2*)&g_dst[i0] = d;
            int2 r;
            r.x = atomicAdd(&g_deg[d.x], 1);
            r.y = atomicAdd(&g_deg[d.y], 1);
            *(int2*)&g_rank[i0] = r;
        }
        if (i0 < N_NODES) {
            int2 g = *(const int2*)&((const int*)batch)[i0];
            *(int2*)&g_batch[i0] = g;
            atomicAdd(&g_gcnt[g.x], 1.f); atomicAdd(&g_gcnt[g.y], 1.f);
        }
    }
}

// ---------------- bucket fill (atomic-free) ----------------
__global__ void fill_csr() {
    int i0 = (blockIdx.x * blockDim.x + threadIdx.x) * 4;
    if (i0 + 3 < N_EDGES) {
        int4 d = *(const int4*)&g_dst[i0];
        int4 s = *(const int4*)&g_src[i0];
        int4 r = *(const int4*)&g_rank[i0];
        if (r.x < CAP) g_csrc[d.x * CAP + r.x] = s.x;
        if (r.y < CAP) g_csrc[d.y * CAP + r.y] = s.y;
        if (r.z < CAP) g_csrc[d.z * CAP + r.z] = s.z;
        if (r.w < CAP) g_csrc[d.w * CAP + r.w] = s.w;
    } else {
        for (int i = i0; i < N_EDGES; ++i) {
            int r = g_rank[i];
            if (r < CAP) g_csrc[g_dst[i] * CAP + r] = g_src[i];
        }
    }
}

// ---------------- standalone gather: 1 node/warp (fine-grained balance) ----------------
// half-warps pair edges; LDG.128 (8 bf16 channels/lane); packed f32x2 accum;
// 8-edge unroll (R13's best per-warp efficiency). grid 2500, natural regs.
__global__ void __launch_bounds__(256) gather_kernel(
    const __nv_bfloat16* __restrict__ feat, float* __restrict__ agg)
{
    const int t = threadIdx.x;
    const int lane = t & 31;
    const int w = t >> 5;
    const int half = lane >> 4;           // 0 or 1
    const int chb = (lane & 15) * 8;      // channel base
    int node = blockIdx.x * 8 + w;        // grid 2500 -> exact (20000 nodes)

    unsigned long long acc[4];
    float z = 0.f;
    asm("mov.b64 %0, {%1, %1};" : "=l"(acc[0]) : "f"(z));
    acc[1] = acc[0]; acc[2] = acc[0]; acc[3] = acc[0];
    if (half == 0)                        // self term (GIN eps=0)
        bf8_acc(&feat[(size_t)node * C + chb], acc);
    const int* adj = &g_csrc[node * CAP];
    int deg = g_deg[node];
    if (deg > CAP) deg = CAP;
    int e = 0;
    for (; e + 8 <= deg; e += 8) {        // 4 paired loads in flight
        int s0 = adj[e + half];
        int s1 = adj[e + 2 + half];
        int s2 = adj[e + 4 + half];
        int s3 = adj[e + 6 + half];
        bf8_acc(&feat[(size_t)s0 * C + chb], acc);
        bf8_acc(&feat[(size_t)s1 * C + chb], acc);
        bf8_acc(&feat[(size_t)s2 * C + chb], acc);
        bf8_acc(&feat[(size_t)s3 * C + chb], acc);
    }
    for (; e + 2 <= deg; e += 2) {
        int s = adj[e + half];
        bf8_acc(&feat[(size_t)s * C + chb], acc);
    }
    if (e < deg && half == 0)
        bf8_acc(&feat[(size_t)adj[e] * C + chb], acc);
    // unpack, combine halves, tf32-round, store
    float av[8];
#pragma unroll
    for (int j = 0; j < 4; ++j) {
        uint32_t lo, hi;
        asm("mov.b64 {%0, %1}, %2;" : "=r"(lo), "=r"(hi) : "l"(acc[j]));
        av[j * 2]     = __uint_as_float(lo);
        av[j * 2 + 1] = __uint_as_float(hi);
    }
#pragma unroll
    for (int j = 0; j < 8; ++j)
        av[j] += __shfl_xor_sync(0xFFFFFFFFu, av[j], 16);
    float4 o = (half == 0)
        ? make_float4(tf32r(av[0]), tf32r(av[1]), tf32r(av[2]), tf32r(av[3]))
        : make_float4(tf32r(av[4]), tf32r(av[5]), tf32r(av[6]), tf32r(av[7]));
    *(float4*)&agg[(size_t)node * C + chb + half * 4] = o;
}

// ---------------- MLP kernel: GEMM1 + ReLU + GEMM2 (+pool) ----------------
#define TILE_ROWS 32
#define ASTR 132
#define WSTR 136
#define CONV_SMEM ((128 * WSTR + TILE_ROWS * ASTR) * 4)

__device__ __forceinline__ void gemm_tile(const float* __restrict__ As,
                                          const float* __restrict__ Ws,
                                          float acc[4][4],
                                          int m_base, int n_base, int qid, int tid4)
{
#pragma unroll
    for (int nt = 0; nt < 4; ++nt)
#pragma unroll
        for (int j = 0; j < 4; ++j) acc[nt][j] = 0.f;

#pragma unroll
    for (int k0 = 0; k0 < 128; k0 += 8) {
        const float* ar0 = &As[(m_base + qid) * ASTR + k0 + tid4];
        const float* ar1 = &As[(m_base + qid + 8) * ASTR + k0 + tid4];
        uint32_t a0 = __float_as_uint(ar0[0]);
        uint32_t a1 = __float_as_uint(ar1[0]);
        uint32_t a2 = __float_as_uint(ar0[4]);
        uint32_t a3 = __float_as_uint(ar1[4]);
        const float* wr0 = &Ws[(k0 + tid4) * WSTR + n_base + qid];
        const float* wr1 = wr0 + 4 * WSTR;
#pragma unroll
        for (int nt = 0; nt < 4; ++nt) {
            uint32_t b0 = __float_as_uint(wr0[nt * 8]);
            uint32_t b1 = __float_as_uint(wr1[nt * 8]);
            mma8(acc[nt], a0, a1, a2, a3, b0, b1);
        }
    }
}

__global__ void __launch_bounds__(256, 2) mlp_kernel(
    const float* __restrict__ agg,
    const float* __restrict__ Wa, const float* __restrict__ ba,
    const float* __restrict__ Wb, const float* __restrict__ bb,
    __nv_bfloat16* __restrict__ outb, int do_pool)
{
    extern __shared__ float sm[];
    float* Ws = sm;                       // [128][WSTR]
    float* As = sm + 128 * WSTR;          // [32][ASTR]

    const int t = threadIdx.x;
    const int m0 = blockIdx.x * TILE_ROWS;
    const int lane = t & 31;
    const int w = t >> 5;

    // load Wa (pure copy, pre-rounded)
#pragma unroll
    for (int i = 0; i < 16; ++i) {
        int idx = t + i * 256;
        float4 v = ((const float4*)Wa)[idx];
        *(float4*)&Ws[(idx >> 5) * WSTR + (idx & 31) * 4] = v;
    }
    // load A tile (coalesced; already tf32-rounded)
#pragma unroll
    for (int i = 0; i < 4; ++i) {
        int idx = t + i * 256;            // 1024 float4
        int r = idx >> 5;
        int c4 = idx & 31;
        float4 v = ((const float4*)agg)[(size_t)(m0 + r) * 32 + c4];
        *(float4*)&As[r * ASTR + c4 * 4] = v;
    }
    __syncthreads();

    const int warp_m = w & 1;
    const int warp_n = w >> 1;
    const int m_base = warp_m * 16;
    const int n_base = warp_n * 32;
    const int qid = lane >> 2;
    const int tid4 = lane & 3;

    float acc[4][4];

    // GEMM1
    gemm_tile(As, Ws, acc, m_base, n_base, qid, tid4);
    __syncthreads();

    // t = tf32(relu(acc + ba)) -> As ; reload Ws with Wb
#pragma unroll
    for (int nt = 0; nt < 4; ++nt) {
        int col = n_base + nt * 8 + 2 * tid4;
        float2 bv = *(const float2*)&ba[col];
        int r0 = m_base + qid, r1 = r0 + 8;
        *(float2*)&As[r0 * ASTR + col] =
            make_float2(tf32r(fmaxf(acc[nt][0] + bv.x, 0.f)),
                        tf32r(fmaxf(acc[nt][1] + bv.y, 0.f)));
        *(float2*)&As[r1 * ASTR + col] =
            make_float2(tf32r(fmaxf(acc[nt][2] + bv.x, 0.f)),
                        tf32r(fmaxf(acc[nt][3] + bv.y, 0.f)));
    }
#pragma unroll
    for (int i = 0; i < 16; ++i) {
        int idx = t + i * 256;
        float4 v = ((const float4*)Wb)[idx];
        *(float4*)&Ws[(idx >> 5) * WSTR + (idx & 31) * 4] = v;
    }
    __syncthreads();

    // GEMM2
    gemm_tile(As, Ws, acc, m_base, n_base, qid, tid4);

    // epilogue
    const int rowA = m0 + m_base + qid;
    const int rowB = rowA + 8;
    if (do_pool) {
        int gA = g_batch[rowA];
        int gB = g_batch[rowB];
#pragma unroll
        for (int nt = 0; nt < 4; ++nt) {
            int col = n_base + nt * 8 + 2 * tid4;
            float2 bv = *(const float2*)&bb[col];
            float v0 = fmaxf(acc[nt][0] + bv.x, 0.f);
            float v1 = fmaxf(acc[nt][1] + bv.y, 0.f);
            float v2 = fmaxf(acc[nt][2] + bv.x, 0.f);
            float v3 = fmaxf(acc[nt][3] + bv.y, 0.f);
            if (gA == gB) {
                atomicAdd(&g_gsum[gA * C + col],     v0 + v2);
                atomicAdd(&g_gsum[gA * C + col + 1], v1 + v3);
            } else {
                atomicAdd(&g_gsum[gA * C + col],     v0);
                atomicAdd(&g_gsum[gA * C + col + 1], v1);
                atomicAdd(&g_gsum[gB * C + col],     v2);
                atomicAdd(&g_gsum[gB * C + col + 1], v3);
            }
        }
    } else {
#pragma unroll
        for (int nt = 0; nt < 4; ++nt) {
            int col = n_base + nt * 8 + 2 * tid4;
            float2 bv = *(const float2*)&bb[col];
            __nv_bfloat162 pA = __float22bfloat162_rn(
                make_float2(fmaxf(acc[nt][0] + bv.x, 0.f), fmaxf(acc[nt][1] + bv.y, 0.f)));
            __nv_bfloat162 pB = __float22bfloat162_rn(
                make_float2(fmaxf(acc[nt][2] + bv.x, 0.f), fmaxf(acc[nt][3] + bv.y, 0.f)));
            *(__nv_bfloat162*)&outb[(size_t)rowA * C + col] = pA;
            *(__nv_bfloat162*)&outb[(size_t)rowB * C + col] = pB;
        }
    }
}

// ---------------- finalize ----------------
__global__ void finalize_kernel(const float* __restrict__ fc_w,
                                const float* __restrict__ fc_b,
                                float* __restrict__ out) {
    int g = blockIdx.x;
    int t = threadIdx.x;  // 128
    float v = g_gsum[g * C + t] * fc_w[t];
#pragma unroll
    for (int o = 16; o > 0; o >>= 1) v += __shfl_down_sync(0xFFFFFFFFu, v, o);
    __shared__ float ws[4];
    if ((t & 31) == 0) ws[t >> 5] = v;
    __syncthreads();
    if (t == 0) {
        float s = ws[0] + ws[1] + ws[2] + ws[3];
        out[g] = s / fmaxf(g_gcnt[g], 1.0f) + fc_b[0];
    }
}

// ---------------- launch ----------------
extern "C" void kernel_launch(void* const* d_in, const int* in_sizes, int n_in,
                              void* d_out, int out_size) {
    const float* x    = (const float*)d_in[0];
    const void*  eidx = d_in[1];
    const void*  batv = d_in[2];
    const float* W1a  = (const float*)d_in[3];
    const float* b1a  = (const float*)d_in[4];
    const float* W1b  = (const float*)d_in[5];
    const float* b1b  = (const float*)d_in[6];
    const float* W2a  = (const float*)d_in[7];
    const float* b2a  = (const float*)d_in[8];
    const float* W2b  = (const float*)d_in[9];
    const float* b2b  = (const float*)d_in[10];
    const float* fcw  = (const float*)d_in[11];
    const float* fcb  = (const float*)d_in[12];
    float* out = (float*)d_out;
    (void)in_sizes; (void)n_in; (void)out_size;

    cudaFuncSetAttribute(mlp_kernel,
                         cudaFuncAttributeMaxDynamicSharedMemorySize, CONV_SMEM);

    float *p_Wt, *p_agg;
    __nv_bfloat16 *p_xb, *p_hb;
    cudaGetSymbolAddress((void**)&p_Wt,  g_Wt);
    cudaGetSymbolAddress((void**)&p_agg, g_agg);
    cudaGetSymbolAddress((void**)&p_xb,  g_xb);
    cudaGetSymbolAddress((void**)&p_hb,  g_hb);

    const int mlp_blocks = N_NODES / TILE_ROWS;      // 625, exact
    const int gather_blocks = N_NODES / 8;           // 2500, exact (1 node/warp)

    // #1: setup + W preround + x->bf16
    mega_setup<<<(N_NODES * C / 8 + 255) / 256, 256>>>(
        x, W1a, W1b, W2a, W2b, (const int*)eidx);
    // #2: index convert + degree histogram (2 edges/thread)
    convert_indices<<<(N_EDGES / 2 + 255) / 256, 256>>>(eidx, batv);
    // #3: bucket fill
    fill_csr<<<(N_EDGES / 4 + 255) / 256, 256>>>();
    // #4 (ncu-profiled): gather layer 1
    gather_kernel<<<gather_blocks, 256>>>(p_xb, p_agg);
    // #5: MLP layer 1 -> h1 (bf16)
    mlp_kernel<<<mlp_blocks, 256, CONV_SMEM>>>(
        p_agg, p_Wt + 0 * C * C, b1a, p_Wt + 1 * C * C, b1b, p_hb, 0);
    // #6: gather layer 2
    gather_kernel<<<gather_blocks, 256>>>(p_hb, p_agg);
    // #7: MLP layer 2 (+ fused pool)
    mlp_kernel<<<mlp_blocks, 256, CONV_SMEM>>>(
        p_agg, p_Wt + 2 * C * C, b2a, p_Wt + 3 * C * C, b2b, nullptr, 1);
    // #8: finalize
    finalize_kernel<<<NUM_GRAPHS, C>>>(fcw, fcb, out);
}